// round 1
// baseline (speedup 1.0000x reference)
#include <cuda_runtime.h>

#define NN 50000
#define NE 500000
#define DN 128
#define DE 64
#define KM 192   // DN + DE   (message GEMM K)
#define KA 256   // 2*DN      (update GEMM K)
#define KE 320   // 2*DN + DE (edge GEMM K)
#define HM 64    // MLP hidden

// ---- scratch (device globals: allocation-free) ----
__device__ float g_x[NN * DN];     // current node features
__device__ float g_ea[NE * DE];    // current edge features
__device__ float g_agg[NN * DN];   // scatter accumulator
__device__ float g_cnt[NN];        // in-degree counts

// ---------------------------------------------------------------------------
__global__ void cnt_kernel(const int* __restrict__ dst) {
    int e = blockIdx.x * blockDim.x + threadIdx.x;
    if (e < NE) atomicAdd(&g_cnt[dst[e]], 1.0f);
}

// ---------------------------------------------------------------------------
// Message: m = relu([x[src], ea] @ Wm + bm); atomicAdd into g_agg[dst].
// TILE = 64 edges / block-iter, 256 threads, each thread: 4 edges x 8 cols.
__global__ void __launch_bounds__(256, 1)
msg_kernel(const float* __restrict__ x, const float* __restrict__ ea,
           const int* __restrict__ src, const int* __restrict__ dst,
           const float* __restrict__ W, const float* __restrict__ b) {
    extern __shared__ float sm[];
    float* Ws  = sm;                   // KM*DN
    float* bs  = Ws + KM * DN;         // DN
    float* ins = bs + DN;              // 64*KM
    int*   ssrc = (int*)(ins + 64 * KM);
    int*   sdst = ssrc + 64;

    const int t = threadIdx.x;
    for (int i = t; i < KM * DN; i += 256) Ws[i] = W[i];
    if (t < DN) bs[t] = b[t];

    const int tx = t & 15;   // cols 8*tx .. 8*tx+7
    const int ty = t >> 4;   // 0..15 -> edges ty*4 .. ty*4+3
    const int ntiles = (NE + 63) >> 6;

    for (int tile = blockIdx.x; tile < ntiles; tile += gridDim.x) {
        __syncthreads();
        if (t < 64) {
            int e = (tile << 6) + t;
            ssrc[t] = (e < NE) ? src[e] : -1;
            sdst[t] = (e < NE) ? dst[e] : -1;
        }
        __syncthreads();
        for (int idx = t; idx < 64 * KM; idx += 256) {
            int it = idx / KM;
            int c  = idx - it * KM;
            int s  = ssrc[it];
            float v = 0.f;
            if (s >= 0) {
                int e = (tile << 6) + it;
                v = (c < DN) ? x[s * DN + c] : ea[e * DE + (c - DN)];
            }
            ins[idx] = v;
        }
        __syncthreads();

        float acc[4][8];
#pragma unroll
        for (int ii = 0; ii < 4; ++ii)
#pragma unroll
            for (int c = 0; c < 8; ++c) acc[ii][c] = 0.f;

        const float* inp = ins + (ty * 4) * KM;
#pragma unroll 2
        for (int k = 0; k < KM; ++k) {
            float4 wa = *(const float4*)(Ws + k * DN + 8 * tx);
            float4 wb = *(const float4*)(Ws + k * DN + 8 * tx + 4);
#pragma unroll
            for (int ii = 0; ii < 4; ++ii) {
                float v = inp[ii * KM + k];
                acc[ii][0] += v * wa.x; acc[ii][1] += v * wa.y;
                acc[ii][2] += v * wa.z; acc[ii][3] += v * wa.w;
                acc[ii][4] += v * wb.x; acc[ii][5] += v * wb.y;
                acc[ii][6] += v * wb.z; acc[ii][7] += v * wb.w;
            }
        }

#pragma unroll
        for (int ii = 0; ii < 4; ++ii) {
            int it = ty * 4 + ii;
            int d  = sdst[it];
            if (d >= 0) {
                float* ag = g_agg + d * DN + 8 * tx;
#pragma unroll
                for (int c = 0; c < 8; ++c) {
                    float m = acc[ii][c] + bs[8 * tx + c];
                    if (m > 0.f) atomicAdd(ag + c, m);  // relu; skip zeros
                }
            }
        }
    }
}

// ---------------------------------------------------------------------------
// Update: x = L2norm(relu([agg/cnt, x] @ Wa + ba)).  TILE=64 nodes, 4x8/thread.
__global__ void __launch_bounds__(256, 1)
upd_kernel(const float* __restrict__ xin,
           const float* __restrict__ W, const float* __restrict__ b) {
    extern __shared__ float sm[];
    float* Ws   = sm;                 // KA*DN
    float* bs   = Ws + KA * DN;       // DN
    float* ins  = bs + DN;            // 64*KA
    float* sinv = ins + 64 * KA;      // 64

    const int t = threadIdx.x;
    for (int i = t; i < KA * DN; i += 256) Ws[i] = W[i];
    if (t < DN) bs[t] = b[t];

    const int tx = t & 15;
    const int ty = t >> 4;
    const int ntiles = (NN + 63) >> 6;

    for (int tile = blockIdx.x; tile < ntiles; tile += gridDim.x) {
        __syncthreads();
        if (t < 64) {
            int i = (tile << 6) + t;
            float c = (i < NN) ? g_cnt[i] : 1.f;
            sinv[t] = 1.f / fmaxf(c, 1.f);
        }
        __syncthreads();
        for (int idx = t; idx < 64 * KA; idx += 256) {
            int it = idx >> 8;        // KA == 256
            int c  = idx & 255;
            int i  = (tile << 6) + it;
            float v = 0.f;
            if (i < NN)
                v = (c < DN) ? g_agg[i * DN + c] * sinv[it]
                             : xin[i * DN + (c - DN)];
            ins[idx] = v;
        }
        __syncthreads();

        float acc[4][8];
#pragma unroll
        for (int ii = 0; ii < 4; ++ii)
#pragma unroll
            for (int c = 0; c < 8; ++c) acc[ii][c] = 0.f;

        const float* inp = ins + (ty * 4) * KA;
#pragma unroll 2
        for (int k = 0; k < KA; ++k) {
            float4 wa = *(const float4*)(Ws + k * DN + 8 * tx);
            float4 wb = *(const float4*)(Ws + k * DN + 8 * tx + 4);
#pragma unroll
            for (int ii = 0; ii < 4; ++ii) {
                float v = inp[ii * KA + k];
                acc[ii][0] += v * wa.x; acc[ii][1] += v * wa.y;
                acc[ii][2] += v * wa.z; acc[ii][3] += v * wa.w;
                acc[ii][4] += v * wb.x; acc[ii][5] += v * wb.y;
                acc[ii][6] += v * wb.z; acc[ii][7] += v * wb.w;
            }
        }

#pragma unroll
        for (int ii = 0; ii < 4; ++ii) {
            int it = ty * 4 + ii;
            int i  = (tile << 6) + it;
            float s = 0.f;
#pragma unroll
            for (int c = 0; c < 8; ++c) {
                float v = fmaxf(acc[ii][c] + bs[8 * tx + c], 0.f);
                acc[ii][c] = v;
                s += v * v;
            }
            // reduce over the 16 lanes (tx group) owning this row
            s += __shfl_xor_sync(0xffffffffu, s, 8);
            s += __shfl_xor_sync(0xffffffffu, s, 4);
            s += __shfl_xor_sync(0xffffffffu, s, 2);
            s += __shfl_xor_sync(0xffffffffu, s, 1);
            float scale = 1.f / fmaxf(sqrtf(s), 1e-12f);
            if (i < NN) {
                float* xo = g_x + i * DN + 8 * tx;
#pragma unroll
                for (int c = 0; c < 8; ++c) xo[c] = acc[ii][c] * scale;
            }
        }
    }
}

// ---------------------------------------------------------------------------
// Edge update: ea = relu([x[src], x[dst], ea] @ We + be).  TILE=64, 4x4/thread.
__global__ void __launch_bounds__(256, 1)
edge_kernel(const float* __restrict__ eain,
            const int* __restrict__ src, const int* __restrict__ dst,
            const float* __restrict__ W, const float* __restrict__ b) {
    extern __shared__ float sm[];
    float* Ws  = sm;                  // KE*DE
    float* bs  = Ws + KE * DE;        // DE
    float* ins = bs + DE;             // 64*KE
    int*   ssrc = (int*)(ins + 64 * KE);
    int*   sdst = ssrc + 64;

    const int t = threadIdx.x;
    for (int i = t; i < KE * DE; i += 256) Ws[i] = W[i];
    if (t < DE) bs[t] = b[t];

    const int tx = t & 15;   // cols 4*tx .. 4*tx+3  (DE=64)
    const int ty = t >> 4;   // 0..15 -> edges ty*4 ..
    const int ntiles = (NE + 63) >> 6;

    for (int tile = blockIdx.x; tile < ntiles; tile += gridDim.x) {
        __syncthreads();
        if (t < 64) {
            int e = (tile << 6) + t;
            ssrc[t] = (e < NE) ? src[e] : -1;
            sdst[t] = (e < NE) ? dst[e] : -1;
        }
        __syncthreads();
        for (int idx = t; idx < 64 * KE; idx += 256) {
            int it = idx / KE;
            int c  = idx - it * KE;
            int s  = ssrc[it];
            float v = 0.f;
            if (s >= 0) {
                int e = (tile << 6) + it;
                v = (c < DN)      ? g_x[s * DN + c]
                  : (c < 2 * DN)  ? g_x[sdst[it] * DN + (c - DN)]
                                  : eain[e * DE + (c - 2 * DN)];
            }
            ins[idx] = v;
        }
        __syncthreads();

        float acc[4][4];
#pragma unroll
        for (int ii = 0; ii < 4; ++ii)
#pragma unroll
            for (int c = 0; c < 4; ++c) acc[ii][c] = 0.f;

        const float* inp = ins + (ty * 4) * KE;
#pragma unroll 2
        for (int k = 0; k < KE; ++k) {
            float4 w = *(const float4*)(Ws + k * DE + 4 * tx);
#pragma unroll
            for (int ii = 0; ii < 4; ++ii) {
                float v = inp[ii * KE + k];
                acc[ii][0] += v * w.x; acc[ii][1] += v * w.y;
                acc[ii][2] += v * w.z; acc[ii][3] += v * w.w;
            }
        }

#pragma unroll
        for (int ii = 0; ii < 4; ++ii) {
            int e = (tile << 6) + ty * 4 + ii;
            if (e < NE) {
                float* eo = g_ea + e * DE + 4 * tx;
#pragma unroll
                for (int c = 0; c < 4; ++c)
                    eo[c] = fmaxf(acc[ii][c] + bs[4 * tx + c], 0.f);
            }
        }
    }
}

// ---------------------------------------------------------------------------
// Head MLP: out = relu(x@W1+b1) @ W2 + b2.  TILE=32 nodes.
__global__ void __launch_bounds__(256, 1)
head_kernel(const float* __restrict__ W1, const float* __restrict__ b1,
            const float* __restrict__ W2, const float* __restrict__ b2,
            float* __restrict__ out) {
    extern __shared__ float sm[];
    float* W1s = sm;                    // DN*HM
    float* b1s = W1s + DN * HM;         // HM
    float* W2s = b1s + HM;              // HM*DN
    float* b2s = W2s + HM * DN;         // DN
    float* ins = b2s + DN;              // 32*DN
    float* hs  = ins + 32 * DN;         // 32*HM

    const int t = threadIdx.x;
    for (int i = t; i < DN * HM; i += 256) W1s[i] = W1[i];
    for (int i = t; i < HM * DN; i += 256) W2s[i] = W2[i];
    if (t < HM) b1s[t] = b1[t];
    if (t < DN) b2s[t] = b2[t];

    const int tx1 = t & 15, ty1 = t >> 4;  // stage1: 2 nodes x 4 cols (HM=64)
    const int tx2 = t & 31, ty2 = t >> 5;  // stage2: 4 nodes x 4 cols (DN=128)
    const int ntiles = (NN + 31) >> 5;

    for (int tile = blockIdx.x; tile < ntiles; tile += gridDim.x) {
        __syncthreads();
        for (int idx = t; idx < 32 * DN; idx += 256) {
            int it = idx >> 7, c = idx & 127;
            int i = (tile << 5) + it;
            ins[idx] = (i < NN) ? g_x[i * DN + c] : 0.f;
        }
        __syncthreads();
        {   // stage 1: h = relu(x @ W1 + b1)
            float acc[2][4] = {{0,0,0,0},{0,0,0,0}};
            const float* inp = ins + (ty1 * 2) * DN;
#pragma unroll 2
            for (int k = 0; k < DN; ++k) {
                float4 w = *(const float4*)(W1s + k * HM + 4 * tx1);
                float v0 = inp[k], v1 = inp[DN + k];
                acc[0][0] += v0 * w.x; acc[0][1] += v0 * w.y;
                acc[0][2] += v0 * w.z; acc[0][3] += v0 * w.w;
                acc[1][0] += v1 * w.x; acc[1][1] += v1 * w.y;
                acc[1][2] += v1 * w.z; acc[1][3] += v1 * w.w;
            }
#pragma unroll
            for (int jj = 0; jj < 2; ++jj) {
                int it = ty1 * 2 + jj;
#pragma unroll
                for (int c = 0; c < 4; ++c)
                    hs[it * HM + 4 * tx1 + c] =
                        fmaxf(acc[jj][c] + b1s[4 * tx1 + c], 0.f);
            }
        }
        __syncthreads();
        {   // stage 2: out = h @ W2 + b2
            float acc[4][4];
#pragma unroll
            for (int ii = 0; ii < 4; ++ii)
#pragma unroll
                for (int c = 0; c < 4; ++c) acc[ii][c] = 0.f;
            const float* inp = hs + (ty2 * 4) * HM;
#pragma unroll 2
            for (int k = 0; k < HM; ++k) {
                float4 w = *(const float4*)(W2s + k * DN + 4 * tx2);
#pragma unroll
                for (int ii = 0; ii < 4; ++ii) {
                    float v = inp[ii * HM + k];
                    acc[ii][0] += v * w.x; acc[ii][1] += v * w.y;
                    acc[ii][2] += v * w.z; acc[ii][3] += v * w.w;
                }
            }
#pragma unroll
            for (int ii = 0; ii < 4; ++ii) {
                int i = (tile << 5) + ty2 * 4 + ii;
                if (i < NN) {
                    float* o = out + i * DN + 4 * tx2;
#pragma unroll
                    for (int c = 0; c < 4; ++c)
                        o[c] = acc[ii][c] + b2s[4 * tx2 + c];
                }
            }
        }
    }
}

// ---------------------------------------------------------------------------
extern "C" void kernel_launch(void* const* d_in, const int* in_sizes, int n_in,
                              void* d_out, int out_size) {
    (void)in_sizes; (void)n_in; (void)out_size;
    const float* x  = (const float*)d_in[0];
    const float* ea = (const float*)d_in[1];
    const int*   ei = (const int*)d_in[2];
    const float* Wm = (const float*)d_in[3];
    const float* bm = (const float*)d_in[4];
    const float* Wa = (const float*)d_in[5];
    const float* ba = (const float*)d_in[6];
    const float* We = (const float*)d_in[7];
    const float* be = (const float*)d_in[8];
    const float* W1 = (const float*)d_in[9];
    const float* b1 = (const float*)d_in[10];
    const float* W2 = (const float*)d_in[11];
    const float* b2 = (const float*)d_in[12];
    float* out = (float*)d_out;
    const int* src = ei;
    const int* dst = ei + NE;

    int nsm = 0;
    cudaDeviceGetAttribute(&nsm, cudaDevAttrMultiProcessorCount, 0);
    if (nsm <= 0) nsm = 148;

    const int SM_MSG = (KM * DN + DN + 64 * KM) * 4 + 64 * 8;
    const int SM_UPD = (KA * DN + DN + 64 * KA + 64) * 4;
    const int SM_EDG = (KE * DE + DE + 64 * KE) * 4 + 64 * 8;
    const int SM_HED = (DN * HM + HM + HM * DN + DN + 32 * DN + 32 * HM) * 4;

    cudaFuncSetAttribute(msg_kernel,  cudaFuncAttributeMaxDynamicSharedMemorySize, SM_MSG);
    cudaFuncSetAttribute(upd_kernel,  cudaFuncAttributeMaxDynamicSharedMemorySize, SM_UPD);
    cudaFuncSetAttribute(edge_kernel, cudaFuncAttributeMaxDynamicSharedMemorySize, SM_EDG);
    cudaFuncSetAttribute(head_kernel, cudaFuncAttributeMaxDynamicSharedMemorySize, SM_HED);

    void *agg_addr = 0, *cnt_addr = 0, *x_addr = 0, *ea_addr = 0;
    cudaGetSymbolAddress(&agg_addr, g_agg);
    cudaGetSymbolAddress(&cnt_addr, g_cnt);
    cudaGetSymbolAddress(&x_addr,  g_x);
    cudaGetSymbolAddress(&ea_addr, g_ea);

    cudaMemsetAsync(cnt_addr, 0, NN * sizeof(float));
    cnt_kernel<<<(NE + 255) / 256, 256>>>(dst);

    for (int l = 0; l < 3; ++l) {
        const float* xl  = (l == 0) ? x  : (const float*)x_addr;
        const float* eal = (l == 0) ? ea : (const float*)ea_addr;
        cudaMemsetAsync(agg_addr, 0, (size_t)NN * DN * sizeof(float));
        msg_kernel<<<nsm, 256, SM_MSG>>>(xl, eal, src, dst,
                                         Wm + l * KM * DN, bm + l * DN);
        upd_kernel<<<nsm, 256, SM_UPD>>>(xl, Wa + l * KA * DN, ba + l * DN);
        edge_kernel<<<nsm, 256, SM_EDG>>>(eal, src, dst,
                                          We + l * KE * DE, be + l * DE);
    }
    head_kernel<<<nsm, 256, SM_HED>>>(W1, b1, W2, b2, out);
}